// round 15
// baseline (speedup 1.0000x reference)
#include <cuda_runtime.h>
#include <cuda_fp16.h>
#include <cstdint>

#define B_    4
#define C_    64
#define H_    128
#define W_    128
#define HW_   16384
#define COUT_ 64
#define KK_   9

// ---- smem byte layout ----
#define S_OFF      0          // S fp16: 256 rows x 128B, XOR-swizzled 16B granules (32KB)
#define W0_OFF     32768      // W buf0: fp16 [co][c] 8KB
#define W1_OFF     40960      // W buf1
#define SW_OFF     49152      // per-pixel uint4 {w00,w01,w10,w11} packed half2 (4KB)
#define SIDX_OFF   53248      // per-pixel uint4 {i0,i1,i2,i3} (4KB)
#define SMEM_BYTES 57344

// prep kernel block split
#define NCONV_BLKS 2048       // x-convert: 524288 threads = B*HW*8ch-groups... (B_*HW_*8/256)
#define NW_BLKS    144        // weight prep: 36864/256

// ---- scratch (__device__ globals: allocation-free rule) ----
__device__ __half g_xh[(size_t)B_ * HW_ * C_];                   // NHWC fp16
__device__ __align__(16) unsigned char g_w[KK_ * 8192];          // per tap: fp16 [co][c], pre-swizzled

// ---------------- helpers ----------------
__device__ __forceinline__ uint32_t smem_u32(const void* p) {
    uint32_t a;
    asm("{ .reg .u64 t; cvta.to.shared.u64 t, %1; cvt.u32.u64 %0, t; }" : "=r"(a) : "l"(p));
    return a;
}
__device__ __forceinline__ uint32_t pack_f16(float lo, float hi) {
    uint32_t r;
    asm("cvt.rn.f16x2.f32 %0, %1, %2;" : "=r"(r) : "f"(hi), "f"(lo));
    return r;
}
__device__ __forceinline__ __half2 u2h2(uint32_t u) {
    __half2 h;
    *(uint32_t*)&h = u;
    return h;
}
__device__ __forceinline__ uint32_t h22u(__half2 h) { return *(uint32_t*)&h; }
// corner gather with evict-last L1 priority (lines reused ~9x across taps)
__device__ __forceinline__ uint4 ldg_el(const void* p) {
    uint4 v;
    asm volatile("ld.global.L1::evict_last.v4.u32 {%0,%1,%2,%3}, [%4];"
                 : "=r"(v.x), "=r"(v.y), "=r"(v.z), "=r"(v.w) : "l"(p));
    return v;
}
__device__ __forceinline__ void ldsm_x4(uint32_t* r, uint32_t addr) {
    asm volatile("ldmatrix.sync.aligned.m8n8.x4.shared.b16 {%0,%1,%2,%3}, [%4];"
                 : "=r"(r[0]), "=r"(r[1]), "=r"(r[2]), "=r"(r[3]) : "r"(addr));
}
__device__ __forceinline__ void mma_f16(float* d, const uint32_t* a, uint32_t b0, uint32_t b1) {
    asm volatile(
        "mma.sync.aligned.m16n8k16.row.col.f32.f16.f16.f32 "
        "{%0,%1,%2,%3}, {%4,%5,%6,%7}, {%8,%9}, {%0,%1,%2,%3};"
        : "+f"(d[0]), "+f"(d[1]), "+f"(d[2]), "+f"(d[3])
        : "r"(a[0]), "r"(a[1]), "r"(a[2]), "r"(a[3]), "r"(b0), "r"(b1));
}
__device__ __forceinline__ void cp_async16(uint32_t dst, const void* src) {
    asm volatile("cp.async.ca.shared.global [%0], [%1], 16;" :: "r"(dst), "l"(src) : "memory");
}

// ---------------- fused prepass: x NCHW f32 -> NHWC fp16  +  weight prep ----------------
// Blocks [0, NCONV_BLKS): warp = 32 consecutive px of one 8ch-group; 8 coalesced
// LDG.32 + 4 cvt + 1 STG.128 (scattered stores, merged in L2).
// Blocks [NCONV_BLKS, +NW_BLKS): weight -> fp16 swizzled [k][co][c].
__global__ void prep_kernel(const float* __restrict__ x, const float* __restrict__ w) {
    if (blockIdx.x < NCONV_BLKS) {
        int t   = blockIdx.x * 256 + threadIdx.x;   // 0 .. 524287
        int pix = t & (HW_ - 1);
        int r   = t >> 14;                          // 0..31
        int cg  = r & 7;
        int b   = r >> 3;
        const float* src = x + ((size_t)b * C_ + cg * 8) * HW_ + pix;
        uint32_t h[4];
#pragma unroll
        for (int i = 0; i < 4; ++i) {
            float lo = src[(size_t)(2 * i) * HW_];
            float hi = src[(size_t)(2 * i + 1) * HW_];
            h[i] = pack_f16(lo, hi);
        }
        *(uint4*)&g_xh[(size_t)(b * HW_ + pix) * C_ + cg * 8] = make_uint4(h[0], h[1], h[2], h[3]);
    } else {
        int t = (blockIdx.x - NCONV_BLKS) * 256 + threadIdx.x;
        if (t < KK_ * COUT_ * C_) {
            int k  = t >> 12;
            int rr = t & 4095;
            int co = rr >> 6;
            int c  = rr & 63;
            float v = w[co * (C_ * KK_) + c * KK_ + k];
            int jsw  = (c >> 3) ^ (co & 7);
            int off  = co * 128 + jsw * 16 + (c & 7) * 2;
            *(__half*)(g_w + k * 8192 + off) = __float2half_rn(v);
        }
    }
}

// ---------------- fused deformable conv: 16x16 output tiles ----------------
// One CTA per (b, 16x16 tile): M = 256 pixels x 64 cout. 256 threads = 8 warps.
__global__ __launch_bounds__(256, 2) void deform_main_kernel(
    const float* __restrict__ offset,
    const float* __restrict__ mask,
    const float* __restrict__ bias,
    float* __restrict__ out) {
    extern __shared__ char sm[];
    const uint32_t smb = smem_u32(sm);

    const int tid = threadIdx.x;
    const int wid = tid >> 5;
    const int l   = tid & 31;
    const int blk = blockIdx.x;          // 0..255
    const int b   = blk >> 6;
    const int tl  = blk & 63;            // 8x8 tiles
    const int ho0 = (tl >> 3) * 16;
    const int wo0 = (tl & 7) * 16;

    const __half* __restrict__ xb = g_xh + (size_t)b * (HW_ * C_);

    const int pm0 = (wid & 3) * 64;      // 4 M-warps x 2 N-warps; tile 64px x 32co
    const int co0 = (wid >> 2) * 32;
    const int lrow = l & 15, lhi = l >> 4, lm = lrow & 7;

    float acc[4][4][4];
#pragma unroll
    for (int i = 0; i < 4; ++i)
#pragma unroll
        for (int j = 0; j < 4; ++j)
#pragma unroll
            for (int q = 0; q < 4; ++q) acc[i][j][q] = 0.f;

    auto coords = [&](int k) {
        const int p  = tid;
        const int ho = ho0 + (p >> 4);
        const int wo = wo0 + (p & 15);
        int obase = ((b * 18 + 2 * k) * 128 + ho) * 128 + wo;
        float dy = offset[obase];
        float dx = offset[obase + HW_];
        float m  = mask[((b * 9 + k) * 128 + ho) * 128 + wo];
        float yy = (float)(ho - 1 + (k / 3)) + dy;
        float xx = (float)(wo - 1 + (k % 3)) + dx;
        float y0f = floorf(yy), x0f = floorf(xx);
        float ly = yy - y0f, lx = xx - x0f;
        int y0 = (int)y0f, x0 = (int)x0f;
        int y1 = y0 + 1,   x1 = x0 + 1;
        bool vy0 = (y0 >= 0) & (y0 < H_), vy1 = (y1 >= 0) & (y1 < H_);
        bool vx0 = (x0 >= 0) & (x0 < W_), vx1 = (x1 >= 0) & (x1 < W_);
        int cy0 = min(max(y0, 0), H_ - 1), cy1 = min(max(y1, 0), H_ - 1);
        int cx0 = min(max(x0, 0), W_ - 1), cx1 = min(max(x1, 0), W_ - 1);
        float w00 = (vy0 & vx0) ? (1.f - ly) * (1.f - lx) * m : 0.f;
        float w01 = (vy0 & vx1) ? (1.f - ly) * lx * m : 0.f;
        float w10 = (vy1 & vx0) ? ly * (1.f - lx) * m : 0.f;
        float w11 = (vy1 & vx1) ? ly * lx * m : 0.f;
        *(uint4*)(sm + SW_OFF + p * 16) =
            make_uint4(pack_f16(w00, w00), pack_f16(w01, w01),
                       pack_f16(w10, w10), pack_f16(w11, w11));
        *(uint4*)(sm + SIDX_OFF + p * 16) =
            make_uint4((uint32_t)((cy0 * W_ + cx0) * C_), (uint32_t)((cy0 * W_ + cx1) * C_),
                       (uint32_t)((cy1 * W_ + cx0) * C_), (uint32_t)((cy1 * W_ + cx1) * C_));
    };
    auto load_w = [&](int k, uint32_t woff) {
        const unsigned char* src = g_w + k * 8192 + tid * 16;
        cp_async16(smb + woff + tid * 16, src);
        cp_async16(smb + woff + tid * 16 + 4096, src + 4096);
        asm volatile("cp.async.commit_group;" ::: "memory");
    };

    // ---- prologue: tap 0 coords + weights ----
    load_w(0, W0_OFF);
    coords(0);
    asm volatile("cp.async.wait_group 0;" ::: "memory");
    __syncthreads();

    for (int k = 0; k < KK_; ++k) {
        const uint32_t wcur = (k & 1) ? W1_OFF : W0_OFF;

        // ---- sample: fp16 gathers (evict_last) + half2 bilinear combine ----
#pragma unroll
        for (int it = 0; it < 8; ++it) {
            int u  = tid + 256 * it;   // 8 c8-groups x 256 pixels
            int c8 = u & 7;
            int p  = u >> 3;
            uint4 wq = *(const uint4*)(sm + SW_OFF + p * 16);
            uint4 iq = *(const uint4*)(sm + SIDX_OFF + p * 16);
            const __half* xc = xb + c8 * 8;
            uint4 a0 = ldg_el(xc + iq.x);
            uint4 a1 = ldg_el(xc + iq.y);
            uint4 a2 = ldg_el(xc + iq.z);
            uint4 a3 = ldg_el(xc + iq.w);
            __half2 w0 = u2h2(wq.x), w1 = u2h2(wq.y), w2 = u2h2(wq.z), w3 = u2h2(wq.w);
            uint32_t res[4];
#pragma unroll
            for (int q = 0; q < 4; ++q) {
                __half2 t = __hmul2(u2h2((&a0.x)[q]), w0);
                t = __hfma2(u2h2((&a1.x)[q]), w1, t);
                t = __hfma2(u2h2((&a2.x)[q]), w2, t);
                t = __hfma2(u2h2((&a3.x)[q]), w3, t);
                res[q] = h22u(t);
            }
            int jsw = c8 ^ (p & 7);
            uint32_t off = (uint32_t)(p * 128 + jsw * 16);
            *(uint4*)(sm + S_OFF + off) = make_uint4(res[0], res[1], res[2], res[3]);
        }
        __syncthreads();

        // ---- overlap: prefetch next tap's weights + coords during GEMM ----
        if (k + 1 < KK_) {
            load_w(k + 1, (k & 1) ? W0_OFF : W1_OFF);
            coords(k + 1);
        }

        // ---- fp16 GEMM via mma.sync ----
        const uint32_t aBase = smb + S_OFF + (uint32_t)(pm0 + lrow) * 128;
        const uint32_t bBase = smb + wcur + (uint32_t)(co0 + lrow) * 128;
#pragma unroll
        for (int ks = 0; ks < 4; ++ks) {
            const uint32_t soff = (uint32_t)((((ks << 1) | lhi) ^ lm) << 4);
            uint32_t bh0[4], bh1[4];
            ldsm_x4(bh0, bBase + soff);
            ldsm_x4(bh1, bBase + 2048 + soff);
#pragma unroll
            for (int mf = 0; mf < 4; ++mf) {
                uint32_t ah[4];
                ldsm_x4(ah, aBase + (uint32_t)(mf * 2048) + soff);
                mma_f16(acc[mf][0], ah, bh0[0], bh0[2]);
                mma_f16(acc[mf][1], ah, bh0[1], bh0[3]);
                mma_f16(acc[mf][2], ah, bh1[0], bh1[2]);
                mma_f16(acc[mf][3], ah, bh1[1], bh1[3]);
            }
        }
        if (k + 1 < KK_)
            asm volatile("cp.async.wait_group 0;" ::: "memory");
        __syncthreads();   // protect S / coords / W buffers for next tap
    }

    // ---- epilogue: fragments -> gmem, add bias ----
    const int rr = (l >> 2);
    const int cbase = (l & 3) * 2;
#pragma unroll
    for (int j = 0; j < 4; ++j) {
        int cc = co0 + j * 8 + cbase;
        float b0v = bias[cc], b1v = bias[cc + 1];
        size_t plane0 = (size_t)(b * COUT_ + cc) * HW_;
        size_t plane1 = plane0 + HW_;
#pragma unroll
        for (int mf = 0; mf < 4; ++mf) {
            int p0 = pm0 + mf * 16 + rr;
            int p1 = p0 + 8;
            size_t o00 = plane0 + (size_t)(ho0 + (p0 >> 4)) * W_ + wo0 + (p0 & 15);
            size_t o01 = plane1 + (size_t)(ho0 + (p0 >> 4)) * W_ + wo0 + (p0 & 15);
            size_t o10 = plane0 + (size_t)(ho0 + (p1 >> 4)) * W_ + wo0 + (p1 & 15);
            size_t o11 = plane1 + (size_t)(ho0 + (p1 >> 4)) * W_ + wo0 + (p1 & 15);
            out[o00] = acc[mf][j][0] + b0v;
            out[o01] = acc[mf][j][1] + b1v;
            out[o10] = acc[mf][j][2] + b0v;
            out[o11] = acc[mf][j][3] + b1v;
        }
    }
}

extern "C" void kernel_launch(void* const* d_in, const int* in_sizes, int n_in,
                              void* d_out, int out_size) {
    const float* x      = (const float*)d_in[0];
    const float* offset = (const float*)d_in[1];
    const float* mask   = (const float*)d_in[2];
    const float* weight = (const float*)d_in[3];
    const float* bias   = (const float*)d_in[4];
    float* out = (float*)d_out;

    prep_kernel<<<NCONV_BLKS + NW_BLKS, 256>>>(x, weight);

    cudaFuncSetAttribute(deform_main_kernel,
                         cudaFuncAttributeMaxDynamicSharedMemorySize, SMEM_BYTES);
    deform_main_kernel<<<B_ * 64, 256, SMEM_BYTES>>>(offset, mask, bias, out);
}